// round 7
// baseline (speedup 1.0000x reference)
#include <cuda_runtime.h>
#include <cuda_fp16.h>
#include <cstdint>

// ---------------------------------------------------------------------------
// RGCN conv with history cache — FUSED aggregate+GEMM version.
//   out[n] = history_buffer[n]                       if history_map[n] != -1
//   out[n] = (1/deg) * sum_r (sum_{e: type==r} x[src_e]) @ W_r    otherwise
// The per-relation aggregate tiles are built in SMEM inside the GEMM kernel
// (A never touches DRAM). GEMM = Ah@W + Al@W (fp16 2-term split, mma.sync).
// ---------------------------------------------------------------------------

#define MAX_NODE 100000
#define HID 128
#define NUM_REL 8
#define KDIM (NUM_REL * HID)   // 1024

__device__ __half g_Wh[(size_t)HID * KDIM];   // W transposed: [n][k], fp16
__device__ int  g_active[MAX_NODE];
__device__ int  g_count;
__device__ int  g_is64;

// ======================= PTX helpers =======================================
__device__ __forceinline__ uint32_t smem_u32(const void* p) {
    uint32_t a;
    asm("{ .reg .u64 t; cvta.to.shared.u64 t, %1; cvt.u32.u64 %0, t; }"
        : "=r"(a) : "l"(p));
    return a;
}
#define CP16(dst, src) \
    asm volatile("cp.async.cg.shared.global [%0], [%1], 16;" \
        :: "r"(dst), "l"(src) : "memory")
#define CP_COMMIT() asm volatile("cp.async.commit_group;" ::: "memory")
#define CP_WAIT_ALL() asm volatile("cp.async.wait_all;" ::: "memory")

#define LDSM4(r, a)                                                           \
    asm volatile("ldmatrix.sync.aligned.m8n8.x4.shared.b16 {%0,%1,%2,%3}, [%4];" \
        : "=r"((r)[0]), "=r"((r)[1]), "=r"((r)[2]), "=r"((r)[3]) : "r"(a))

#define MMA16816F16(c, a, b0, b1)                                             \
    asm volatile("mma.sync.aligned.m16n8k16.row.col.f32.f16.f16.f32 "         \
        "{%0,%1,%2,%3}, {%4,%5,%6,%7}, {%8,%9}, {%0,%1,%2,%3};"               \
        : "+f"((c)[0]), "+f"((c)[1]), "+f"((c)[2]), "+f"((c)[3])              \
        : "r"((a)[0]), "r"((a)[1]), "r"((a)[2]), "r"((a)[3]),                 \
          "r"(b0), "r"(b1))

// swizzled byte offset within a [rows][64 f16] tile (row stride 128B, SW128)
__device__ __forceinline__ uint32_t swz(uint32_t row, uint32_t chunk) {
    return row * 128u + ((chunk ^ (row & 7u)) << 4);
}

// ===========================================================================
__global__ void detect_reset_kernel(const void* ptrv) {
    g_count = 0;
    // ptr[0]==0; if int64, word[1] is the high half of 0; if int32 it is deg>=1.
    g_is64 = (((const int*)ptrv)[1] == 0) ? 1 : 0;
}

// Transpose W [1024,128] fp32 -> g_Wh [128][1024] fp16
__global__ void wprep_kernel(const float* __restrict__ W) {
    int i = blockIdx.x * blockDim.x + threadIdx.x;
    if (i >= KDIM * HID) return;
    int k = i >> 7, n = i & 127;
    g_Wh[(size_t)n * KDIM + k] = __float2half(W[i]);
}

// ---------------------------------------------------------------------------
__global__ void compact_history_kernel(const void* __restrict__ hmv,
                                       const float* __restrict__ hb,
                                       float* __restrict__ out,
                                       int dup, int num_node) {
    int w    = (int)((blockIdx.x * blockDim.x + threadIdx.x) >> 5);
    int lane = threadIdx.x & 31;
    if (w >= num_node) return;
    long long m = g_is64 ? ((const long long*)hmv)[w]
                         : (long long)((const int*)hmv)[w];
    if (m != -1LL) {
        float4 v = *(const float4*)(hb + (size_t)w * HID + lane * 4);
        *(float4*)(out + (size_t)w * HID + lane * 4) = v;
        if (dup)
            *(float4*)(out + (size_t)(w + num_node) * HID + lane * 4) = v;
    } else if (lane == 0) {
        int slot = atomicAdd(&g_count, 1);
        g_active[slot] = w;
    }
}

// ---------------------------------------------------------------------------
// FUSED kernel: CTA = 128 active nodes, 256 threads (8 warps, warp 64x32).
// Loop relations r=0..7: A_r tile (128x128 fp16 hi/lo) built in smem from
// gathered x rows; W_r tile streamed via cp.async; mma.sync accumulates.
//
// SMEM layout (bytes):
//   META  [128][16] u32 packed (src | type<<20)     @ 0       (8192)
//   DEG   [128] int                                 @ 8192    (512)
//   P0    [128] i64 (for deg>16 general tail)       @ 8704    (1024)
//   A     2 bufs x (hi 32768 + lo 32768)            @ 10240   (131072)
//         plane = two k64 sub-tiles (16384 each), SW128 rows
//   W     2 bufs x 32768                            @ 141312  (65536)
#define FBM 128
#define SM_META 0
#define SM_DEG  8192
#define SM_P0   8704
#define SM_A    10240
#define SM_W    141312
#define FUSED_SMEM 206848

__global__ __launch_bounds__(256, 1)
void fused_kernel(const float* __restrict__ x,
                  const void* __restrict__ ptrv,
                  const void* __restrict__ idxv,
                  const void* __restrict__ etv,
                  float* __restrict__ out,
                  int dup, int num_node) {
    extern __shared__ __align__(1024) char smem[];
    int count = g_count;
    int m0 = blockIdx.x * FBM;
    if (m0 >= count) return;

    uint32_t sb = smem_u32(smem);
    int t = threadIdx.x, wid = t >> 5, lane = t & 31;
    int wm = wid >> 2;                  // 0..1 (m block of 64)
    int wn = wid & 3;                   // 0..3 (n block of 32)
    int ltile = lane >> 3, lrow = lane & 7;
    int is64 = g_is64;

    uint32_t*  s_meta = (uint32_t*)(smem + SM_META);
    int*       s_deg  = (int*)(smem + SM_DEG);
    long long* s_p0   = (long long*)(smem + SM_P0);

    // ---- prologue: edge metadata into smem ----
    for (int i = t; i < FBM * 16; i += 256) {
        int nd = i >> 4, e = i & 15;
        int m = m0 + nd;
        uint32_t pk = 0xFu << 20;          // type 15: never matches r<8
        if (m < count) {
            int node = g_active[m];
            long long p0, p1;
            if (is64) { p0 = ((const long long*)ptrv)[node];
                        p1 = ((const long long*)ptrv)[node + 1]; }
            else      { p0 = ((const int*)ptrv)[node];
                        p1 = ((const int*)ptrv)[node + 1]; }
            int dg = (int)(p1 - p0);
            if (e == 0) { s_deg[nd] = dg; s_p0[nd] = p0; }
            if (e < dg) {
                long long ee = p0 + e;
                uint32_t src = is64 ? (uint32_t)((const long long*)idxv)[ee]
                                    : (uint32_t)((const int*)idxv)[ee];
                uint32_t ty  = is64 ? (uint32_t)((const long long*)etv)[ee]
                                    : (uint32_t)((const int*)etv)[ee];
                pk = src | (ty << 20);
            }
        } else if (e == 0) { s_deg[nd] = 0; s_p0[nd] = 0; }
        s_meta[i] = pk;
    }
    __syncthreads();

    // lane's 4 channels within the 128-ch A row -> sub-tile + chunk + rem
    const uint32_t a_sub  = (uint32_t)(lane >> 4) * 16384u;
    const uint32_t a_colb = (uint32_t)(lane & 15) * 8u;
    const uint32_t a_chnk = a_colb >> 4;
    const uint32_t a_rem  = a_colb & 15u;

    // ---- build A_r tile into buffer `buf` (each warp owns 16 rows) ----
    auto build_A = [&](int r, int buf) {
        uint32_t pb = (uint32_t)SM_A + (uint32_t)buf * 65536u + a_sub;
        for (int i = 0; i < 16; i += 2) {      // 2-node interleave (gather MLP)
            int ndA = wid * 16 + i, ndB = ndA + 1;
            float4 aA = make_float4(0.f, 0.f, 0.f, 0.f);
            float4 aB = make_float4(0.f, 0.f, 0.f, 0.f);
            int dgA = s_deg[ndA], dgB = s_deg[ndB];
            int dcA = dgA < 16 ? dgA : 16;
            int dcB = dgB < 16 ? dgB : 16;
            int dc = dcA > dcB ? dcA : dcB;
            for (int e = 0; e < dc; e++) {
                uint32_t pkA = s_meta[ndA * 16 + e];
                uint32_t pkB = s_meta[ndB * 16 + e];
                bool mA = (e < dcA) && ((int)(pkA >> 20) == r);
                bool mB = (e < dcB) && ((int)(pkB >> 20) == r);
                float4 vA, vB;
                if (mA) vA = *(const float4*)(x + (size_t)(pkA & 0xFFFFFu) * HID + lane * 4);
                if (mB) vB = *(const float4*)(x + (size_t)(pkB & 0xFFFFFu) * HID + lane * 4);
                if (mA) { aA.x += vA.x; aA.y += vA.y; aA.z += vA.z; aA.w += vA.w; }
                if (mB) { aB.x += vB.x; aB.y += vB.y; aB.z += vB.z; aB.w += vB.w; }
            }
            // general tail for deg>16 (not taken on this dataset)
            if (dgA > 16 || dgB > 16) {
                for (int s = 0; s < 2; s++) {
                    int nd = s ? ndB : ndA;
                    int dg = s ? dgB : dgA;
                    float4* ap = s ? &aB : &aA;
                    long long p0 = s_p0[nd];
                    for (long long ee = p0 + 16; ee < p0 + dg; ee++) {
                        int ty = is64 ? (int)((const long long*)etv)[ee]
                                      : ((const int*)etv)[ee];
                        if (ty == r) {
                            long long sr = is64 ? ((const long long*)idxv)[ee]
                                                : (long long)((const int*)idxv)[ee];
                            float4 v = *(const float4*)(x + (size_t)sr * HID + lane * 4);
                            ap->x += v.x; ap->y += v.y; ap->z += v.z; ap->w += v.w;
                        }
                    }
                }
            }
            #pragma unroll
            for (int s = 0; s < 2; s++) {
                float4 a = s ? aB : aA;
                uint32_t nd = (uint32_t)(s ? ndB : ndA);
                __half h0 = __float2half(a.x), h1 = __float2half(a.y);
                __half h2 = __float2half(a.z), h3 = __float2half(a.w);
                __half l0 = __float2half(a.x - __half2float(h0));
                __half l1 = __float2half(a.y - __half2float(h1));
                __half l2 = __float2half(a.z - __half2float(h2));
                __half l3 = __float2half(a.w - __half2float(h3));
                uint2 uh, ul;
                uh.x = ((uint32_t)__half_as_ushort(h1) << 16) | __half_as_ushort(h0);
                uh.y = ((uint32_t)__half_as_ushort(h3) << 16) | __half_as_ushort(h2);
                ul.x = ((uint32_t)__half_as_ushort(l1) << 16) | __half_as_ushort(l0);
                ul.y = ((uint32_t)__half_as_ushort(l3) << 16) | __half_as_ushort(l2);
                uint32_t off = pb + nd * 128u + ((a_chnk ^ (nd & 7u)) << 4) + a_rem;
                *(uint2*)(smem + off)           = uh;
                *(uint2*)(smem + off + 32768u)  = ul;
            }
        }
    };

    // ---- W_r tile loader (cp.async) ----
    const __half* pW = (const __half*)g_Wh;
    auto load_W = [&](int r, int buf) {
        uint32_t wb = sb + SM_W + (uint32_t)buf * 32768u;
        #pragma unroll
        for (int i = 0; i < 8; i++) {
            int id  = t + i * 256;          // 0..2047
            int row = id >> 4;              // 0..127
            int c   = id & 15;              // 16B chunk within 256B (two subs)
            uint32_t dst = wb + (uint32_t)(c >> 3) * 16384u
                         + swz((uint32_t)row, (uint32_t)(c & 7));
            CP16(dst, pW + (size_t)row * KDIM + r * 128 + c * 8);
        }
        CP_COMMIT();
    };

    float acc[4][4][4];
    #pragma unroll
    for (int i = 0; i < 4; i++)
        #pragma unroll
        for (int j = 0; j < 4; j++)
            #pragma unroll
            for (int q = 0; q < 4; q++) acc[i][j][q] = 0.f;

    // ---- MMA over one relation block (K=128 = 2 sub-tiles x 4 k16) ----
    auto mma_rel = [&](int buf) {
        uint32_t ahb = sb + SM_A + (uint32_t)buf * 65536u;
        uint32_t alb = ahb + 32768u;
        uint32_t wb  = sb + SM_W + (uint32_t)buf * 32768u;
        #pragma unroll
        for (int ks8 = 0; ks8 < 8; ks8++) {
            uint32_t sof = (uint32_t)(ks8 >> 2) * 16384u;
            int cch = (ks8 & 3) * 2 + (ltile >> 1);
            uint32_t bh[2][4];
            #pragma unroll
            for (int j = 0; j < 2; j++) {
                uint32_t r = wn * 32 + j * 16 + (ltile & 1) * 8 + lrow;
                LDSM4(bh[j], wb + sof + swz(r, (uint32_t)cch));
            }
            #pragma unroll
            for (int mf = 0; mf < 4; mf++) {
                uint32_t ah[4], al[4];
                uint32_t r = wm * 64 + mf * 16 + (ltile & 1) * 8 + lrow;
                uint32_t sw = sof + swz(r, (uint32_t)cch);
                LDSM4(ah, ahb + sw);
                LDSM4(al, alb + sw);
                #pragma unroll
                for (int nf = 0; nf < 4; nf++) {
                    int hj = nf >> 1, ho = nf & 1;
                    MMA16816F16(acc[mf][nf], ah, bh[hj][ho], bh[hj][ho + 2]);
                }
                #pragma unroll
                for (int nf = 0; nf < 4; nf++) {
                    int hj = nf >> 1, ho = nf & 1;
                    MMA16816F16(acc[mf][nf], al, bh[hj][ho], bh[hj][ho + 2]);
                }
            }
        }
    };

    // ---- pipeline: relation r consumed from buf (r&1), r+1 built into other
    load_W(0, 0);
    build_A(0, 0);
    CP_WAIT_ALL();
    __syncthreads();
    for (int r = 0; r < NUM_REL; r++) {
        int cur = r & 1;
        if (r < NUM_REL - 1) load_W(r + 1, cur ^ 1);
        mma_rel(cur);
        if (r < NUM_REL - 1) { build_A(r + 1, cur ^ 1); CP_WAIT_ALL(); }
        __syncthreads();
    }

    // ---- epilogue: 1/deg scale + scatter (both output halves) ----
    int g  = lane >> 2;
    int tq = lane & 3;
    #pragma unroll
    for (int mf = 0; mf < 4; mf++) {
        int nd_lo = wm * 64 + mf * 16 + g;
        #pragma unroll
        for (int half = 0; half < 2; half++) {
            int nd = nd_lo + half * 8;
            int m = m0 + nd;
            if (m >= count) continue;
            int node = g_active[m];
            float inv = 1.0f / (float)s_deg[nd];
            #pragma unroll
            for (int nf = 0; nf < 4; nf++) {
                float2 v;
                v.x = acc[mf][nf][half * 2 + 0] * inv;
                v.y = acc[mf][nf][half * 2 + 1] * inv;
                size_t co = (size_t)node * HID + wn * 32 + nf * 8 + tq * 2;
                *(float2*)(out + co) = v;
                if (dup)
                    *(float2*)(out + co + (size_t)num_node * HID) = v;
            }
        }
    }
}

// ---------------------------------------------------------------------------
extern "C" void kernel_launch(void* const* d_in, const int* in_sizes, int n_in,
                              void* d_out, int out_size) {
    const float* x  = (const float*)d_in[0];
    const float* W  = (const float*)d_in[1];   // [8,128,128] == [1024,128]
    const void*  pt = d_in[2];
    const void*  ix = d_in[3];
    const void*  et = d_in[4];
    const void*  hm = d_in[5];
    const float* hb = (const float*)d_in[6];
    float* out = (float*)d_out;

    int num_node = in_sizes[0] / HID;
    long long need2 = 2LL * (long long)num_node * HID;
    int dup = ((long long)out_size >= need2) ? 1 : 0;

    cudaFuncSetAttribute(fused_kernel,
                         cudaFuncAttributeMaxDynamicSharedMemorySize, FUSED_SMEM);

    detect_reset_kernel<<<1, 1>>>(pt);
    wprep_kernel<<<(KDIM * HID + 255) / 256, 256>>>(W);

    int warp_blocks = (num_node * 32 + 255) / 256;
    compact_history_kernel<<<warp_blocks, 256>>>(hm, hb, out, dup, num_node);
    fused_kernel<<<(num_node + FBM - 1) / FBM, 256, FUSED_SMEM>>>(
        x, pt, ix, et, out, dup, num_node);
}

// round 8
// speedup vs baseline: 2.5980x; 2.5980x over previous
#include <cuda_runtime.h>
#include <cuda_fp16.h>
#include <cstdint>

// ---------------------------------------------------------------------------
// RGCN conv with history cache.
//   out[n] = history_buffer[n]                       if history_map[n] != -1
//   out[n] = (1/deg) * sum_r A_r[n] @ W_r            otherwise
// Aggregate per-relation sums (fp32 accum) into compacted rows, round to a
// single fp16 plane; GEMM = A@W in plain fp16 mma.sync (error ~6e-5 << 1e-3).
// Round 8: round-6 structure, lo-plane removed (halves agg stores, A reads,
// and MMA count).
// ---------------------------------------------------------------------------

#define MAX_NODE 100000
#define PAD_ROWS (MAX_NODE + 256)
#define HID 128
#define NUM_REL 8
#define KDIM (NUM_REL * HID)   // 1024

__device__ __half g_Ah[(size_t)PAD_ROWS * KDIM];
__device__ __half g_Wh[(size_t)HID * KDIM];   // [n][k] (K-major)
__device__ int  g_active[MAX_NODE];
__device__ int  g_count;
__device__ int  g_is64;

// ======================= PTX helpers =======================================
__device__ __forceinline__ uint32_t smem_u32(const void* p) {
    uint32_t a;
    asm("{ .reg .u64 t; cvta.to.shared.u64 t, %1; cvt.u32.u64 %0, t; }"
        : "=r"(a) : "l"(p));
    return a;
}
#define CP16(dst, src) \
    asm volatile("cp.async.cg.shared.global [%0], [%1], 16;" \
        :: "r"(dst), "l"(src) : "memory")
#define CP_COMMIT() asm volatile("cp.async.commit_group;" ::: "memory")
#define CP_WAIT(n)  asm volatile("cp.async.wait_group %0;" :: "n"(n) : "memory")
#define CP_WAIT_ALL() asm volatile("cp.async.wait_all;" ::: "memory")

#define LDSM4(r, a)                                                           \
    asm volatile("ldmatrix.sync.aligned.m8n8.x4.shared.b16 {%0,%1,%2,%3}, [%4];" \
        : "=r"((r)[0]), "=r"((r)[1]), "=r"((r)[2]), "=r"((r)[3]) : "r"(a))

#define MMA16816F16(c, a, b0, b1)                                             \
    asm volatile("mma.sync.aligned.m16n8k16.row.col.f32.f16.f16.f32 "         \
        "{%0,%1,%2,%3}, {%4,%5,%6,%7}, {%8,%9}, {%0,%1,%2,%3};"               \
        : "+f"((c)[0]), "+f"((c)[1]), "+f"((c)[2]), "+f"((c)[3])              \
        : "r"((a)[0]), "r"((a)[1]), "r"((a)[2]), "r"((a)[3]),                 \
          "r"(b0), "r"(b1))

// ===========================================================================
__global__ void detect_reset_kernel(const void* ptrv) {
    g_count = 0;
    // ptr[0]==0; if int64, word[1] is the high half of 0; if int32 it is deg>=1.
    g_is64 = (((const int*)ptrv)[1] == 0) ? 1 : 0;
}

// Transpose W [1024,128] fp32 -> g_Wh [128][1024] fp16
__global__ void wprep_kernel(const float* __restrict__ W) {
    int i = blockIdx.x * blockDim.x + threadIdx.x;
    if (i >= KDIM * HID) return;
    int k = i >> 7, n = i & 127;
    g_Wh[(size_t)n * KDIM + k] = __float2half(W[i]);
}

// ---------------------------------------------------------------------------
__global__ void compact_history_kernel(const void* __restrict__ hmv,
                                       const float* __restrict__ hb,
                                       float* __restrict__ out,
                                       int dup, int num_node) {
    int w    = (int)((blockIdx.x * blockDim.x + threadIdx.x) >> 5);
    int lane = threadIdx.x & 31;
    if (w >= num_node) return;
    long long m = g_is64 ? ((const long long*)hmv)[w]
                         : (long long)((const int*)hmv)[w];
    if (m != -1LL) {
        float4 v = *(const float4*)(hb + (size_t)w * HID + lane * 4);
        *(float4*)(out + (size_t)w * HID + lane * 4) = v;
        if (dup)
            *(float4*)(out + (size_t)(w + num_node) * HID + lane * 4) = v;
    } else if (lane == 0) {
        int slot = atomicAdd(&g_count, 1);
        g_active[slot] = w;
    }
}

// ---------------------------------------------------------------------------
// Aggregate: one warp per node; gathers staged through smem via cp.async
// (MLP=16 with no register gather buffers). Lane owns 4 channels.
__device__ __forceinline__ void store_h(float4 a, size_t off) {
    __half h0 = __float2half(a.x), h1 = __float2half(a.y);
    __half h2 = __float2half(a.z), h3 = __float2half(a.w);
    uint2 uh;
    uh.x = ((uint32_t)__half_as_ushort(h1) << 16) | __half_as_ushort(h0);
    uh.y = ((uint32_t)__half_as_ushort(h3) << 16) | __half_as_ushort(h2);
    *(uint2*)((__half*)g_Ah + off) = uh;
}

#define ACC_CASE(r, a)                                                        \
    case r: a.x += v_.x; a.y += v_.y; a.z += v_.z; a.w += v_.w; break;

#define AGG_CHUNK 16
#define AGG_ROWB  (AGG_CHUNK * HID)     // floats per warp buffer

__global__ __launch_bounds__(256)
void aggregate_kernel(const float* __restrict__ x,
                      const void* __restrict__ ptrv,
                      const void* __restrict__ idxv,
                      const void* __restrict__ etv) {
    extern __shared__ float sbuf[];     // 8 warps * 16 rows * 512B = 64 KB
    int w    = (int)((blockIdx.x * blockDim.x + threadIdx.x) >> 5);
    int lane = threadIdx.x & 31;
    if (w >= g_count) return;
    int is64 = g_is64;
    int node = g_active[w];

    long long p0, p1;
    if (is64) {
        p0 = ((const long long*)ptrv)[node];
        p1 = ((const long long*)ptrv)[node + 1];
    } else {
        p0 = ((const int*)ptrv)[node];
        p1 = ((const int*)ptrv)[node + 1];
    }

    float*   mybuf  = sbuf + (size_t)(threadIdx.x >> 5) * AGG_ROWB;
    uint32_t sm     = smem_u32(mybuf);

    float4 a0 = {0,0,0,0}, a1 = {0,0,0,0}, a2 = {0,0,0,0}, a3 = {0,0,0,0};
    float4 a4 = {0,0,0,0}, a5 = {0,0,0,0}, a6 = {0,0,0,0}, a7 = {0,0,0,0};

    for (long long c0 = p0; c0 < p1; c0 += AGG_CHUNK) {
        int n = (int)((p1 - c0) < AGG_CHUNK ? (p1 - c0) : AGG_CHUNK);
        long long s_l = 0; int t_l = 0;
        if (lane < n) {
            long long e = c0 + lane;
            s_l = is64 ? ((const long long*)idxv)[e]
                       : (long long)((const int*)idxv)[e];
            t_l = is64 ? (int)((const long long*)etv)[e]
                       : ((const int*)etv)[e];
        }
        if (n == AGG_CHUNK) {
            #pragma unroll
            for (int e = 0; e < AGG_CHUNK; e++) {
                long long src = __shfl_sync(0xffffffffu, s_l, e);
                CP16(sm + (uint32_t)(e * 512 + lane * 16),
                     x + (size_t)src * HID + lane * 4);
            }
            CP_WAIT_ALL();
            __syncwarp();
            #pragma unroll
            for (int e = 0; e < AGG_CHUNK; e++) {
                int ty = __shfl_sync(0xffffffffu, t_l, e);
                float4 v_ = *(const float4*)(mybuf + e * HID + lane * 4);
                switch (ty) {
                    ACC_CASE(0, a0) ACC_CASE(1, a1) ACC_CASE(2, a2) ACC_CASE(3, a3)
                    ACC_CASE(4, a4) ACC_CASE(5, a5) ACC_CASE(6, a6) ACC_CASE(7, a7)
                    default: break;
                }
            }
        } else {
            for (int e = 0; e < n; e++) {
                long long src = __shfl_sync(0xffffffffu, s_l, e);
                CP16(sm + (uint32_t)(e * 512 + lane * 16),
                     x + (size_t)src * HID + lane * 4);
            }
            CP_WAIT_ALL();
            __syncwarp();
            for (int e = 0; e < n; e++) {
                int ty = __shfl_sync(0xffffffffu, t_l, e);
                float4 v_ = *(const float4*)(mybuf + e * HID + lane * 4);
                switch (ty) {
                    ACC_CASE(0, a0) ACC_CASE(1, a1) ACC_CASE(2, a2) ACC_CASE(3, a3)
                    ACC_CASE(4, a4) ACC_CASE(5, a5) ACC_CASE(6, a6) ACC_CASE(7, a7)
                    default: break;
                }
            }
        }
        __syncwarp();
    }

    size_t base = (size_t)w * KDIM + lane * 4;
    store_h(a0, base + 0 * HID);  store_h(a1, base + 1 * HID);
    store_h(a2, base + 2 * HID);  store_h(a3, base + 3 * HID);
    store_h(a4, base + 4 * HID);  store_h(a5, base + 5 * HID);
    store_h(a6, base + 6 * HID);  store_h(a7, base + 7 * HID);
}
#define AGG_SMEM (8 * AGG_ROWB * 4)     // 65536 bytes

// ---------------------------------------------------------------------------
// mma.sync GEMM: [count,1024](A fp16) @ [1024,128](W fp16), single term.
// CTA 256x128 (512 thr, 16 warps, warp 64x32), k-tile 64, double-buffered.
#define GBM 256
#define GBK 64
#define NT (KDIM / GBK)                // 16 k-tiles
#define TPA (GBM * GBK * 2)            // 32768 bytes A tile
#define TPB (HID * GBK * 2)            // 16384 bytes B tile
#define S_AH 0
#define S_BH TPA
#define STAGE_B (TPA + TPB)            // 49152 per stage
#define SMEM_BYTES (2 * STAGE_B)       // 98304

// swizzled byte offset within a [rows][64 f16] tile (row stride 128B, SW128)
__device__ __forceinline__ uint32_t swz(uint32_t row, uint32_t chunk) {
    return row * 128u + ((chunk ^ (row & 7u)) << 4);
}

__global__ __launch_bounds__(512, 1)
void gemm_mma_kernel(const void* __restrict__ ptrv,
                     float* __restrict__ out,
                     int dup, int num_node) {
    extern __shared__ __align__(1024) char smem[];
    int count = g_count;
    int m0 = blockIdx.x * GBM;
    if (m0 >= count) return;

    uint32_t sb = smem_u32(smem);
    int t = threadIdx.x, wid = t >> 5, lane = t & 31;
    int wm = wid >> 2;                 // 0..3  (m block of 64)
    int wn = wid & 3;                  // 0..3  (n block of 32)

    const __half* pAh = (const __half*)g_Ah;
    const __half* pWh = (const __half*)g_Wh;

    int ltile = lane >> 3, lrow = lane & 7;

    float acc[4][4][4];
    #pragma unroll
    for (int i = 0; i < 4; i++)
        #pragma unroll
        for (int j = 0; j < 4; j++)
            #pragma unroll
            for (int q = 0; q < 4; q++) acc[i][j][q] = 0.f;

    auto load_stage = [&](int kt) {
        uint32_t stg = sb + (kt & 1) * STAGE_B;
        size_t kofs = (size_t)kt * GBK;
        #pragma unroll
        for (int i = 0; i < 4; i++) {
            int id  = t + i * 512;          // 0..2047
            int row = id >> 3;              // 0..255
            int c   = id & 7;
            uint32_t sw = swz(row, c);
            size_t ga = (size_t)(m0 + row) * KDIM + kofs + c * 8;
            CP16(stg + S_AH + sw, pAh + ga);
        }
        #pragma unroll
        for (int i = 0; i < 2; i++) {
            int id  = t + i * 512;          // 0..1023
            int row = id >> 3;              // 0..127
            int c   = id & 7;
            uint32_t sw = swz(row, c);
            size_t gw = (size_t)row * KDIM + kofs + c * 8;
            CP16(stg + S_BH + sw, pWh + gw);
        }
        CP_COMMIT();
    };

    load_stage(0);

    for (int kt = 0; kt < NT; kt++) {
        if (kt + 1 < NT) { load_stage(kt + 1); CP_WAIT(1); }
        else            { CP_WAIT(0); }
        __syncthreads();

        uint32_t stg = sb + (kt & 1) * STAGE_B;
        #pragma unroll
        for (int ks = 0; ks < 4; ks++) {
            int cch = ks * 2 + (ltile >> 1);
            uint32_t bh[2][4];
            #pragma unroll
            for (int j = 0; j < 2; j++) {
                uint32_t r = wn * 32 + j * 16 + (ltile & 1) * 8 + lrow;
                uint32_t sw = swz(r, (uint32_t)cch);
                LDSM4(bh[j], stg + S_BH + sw);
            }
            #pragma unroll
            for (int mf = 0; mf < 4; mf++) {
                uint32_t ah[4];
                uint32_t r = wm * 64 + mf * 16 + (ltile & 1) * 8 + lrow;
                uint32_t sw = swz(r, (uint32_t)cch);
                LDSM4(ah, stg + S_AH + sw);
                #pragma unroll
                for (int nf = 0; nf < 4; nf++) {
                    int hj = nf >> 1, ho = nf & 1;
                    MMA16816F16(acc[mf][nf], ah, bh[hj][ho], bh[hj][ho + 2]);
                }
            }
        }
        __syncthreads();
    }

    // ---- epilogue: 1/deg scale + scatter (both output halves) ----
    int g  = lane >> 2;
    int tq = lane & 3;
    int is64 = g_is64;
    #pragma unroll
    for (int mf = 0; mf < 4; mf++) {
        int m_lo = m0 + wm * 64 + mf * 16 + g;       // rows g and g+8
        #pragma unroll
        for (int half = 0; half < 2; half++) {
            int m = m_lo + half * 8;
            if (m >= count) continue;
            int node = g_active[m];
            long long d;
            if (is64)
                d = ((const long long*)ptrv)[node + 1] - ((const long long*)ptrv)[node];
            else
                d = (long long)(((const int*)ptrv)[node + 1] - ((const int*)ptrv)[node]);
            float inv = 1.0f / (float)d;
            #pragma unroll
            for (int nf = 0; nf < 4; nf++) {
                float2 v;
                v.x = acc[mf][nf][half * 2 + 0] * inv;
                v.y = acc[mf][nf][half * 2 + 1] * inv;
                size_t co = (size_t)node * HID + wn * 32 + nf * 8 + tq * 2;
                *(float2*)(out + co) = v;
                if (dup)
                    *(float2*)(out + co + (size_t)num_node * HID) = v;
            }
        }
    }
}

// ---------------------------------------------------------------------------
extern "C" void kernel_launch(void* const* d_in, const int* in_sizes, int n_in,
                              void* d_out, int out_size) {
    const float* x  = (const float*)d_in[0];
    const float* W  = (const float*)d_in[1];   // [8,128,128] == [1024,128]
    const void*  pt = d_in[2];
    const void*  ix = d_in[3];
    const void*  et = d_in[4];
    const void*  hm = d_in[5];
    const float* hb = (const float*)d_in[6];
    float* out = (float*)d_out;

    int num_node = in_sizes[0] / HID;
    long long need2 = 2LL * (long long)num_node * HID;
    int dup = ((long long)out_size >= need2) ? 1 : 0;

    cudaFuncSetAttribute(gemm_mma_kernel,
                         cudaFuncAttributeMaxDynamicSharedMemorySize, SMEM_BYTES);
    cudaFuncSetAttribute(aggregate_kernel,
                         cudaFuncAttributeMaxDynamicSharedMemorySize, AGG_SMEM);

    detect_reset_kernel<<<1, 1>>>(pt);
    wprep_kernel<<<(KDIM * HID + 255) / 256, 256>>>(W);

    int warp_blocks = (num_node * 32 + 255) / 256;
    compact_history_kernel<<<warp_blocks, 256>>>(hm, hb, out, dup, num_node);
    aggregate_kernel<<<warp_blocks, 256, AGG_SMEM>>>(x, pt, ix, et);
    gemm_mma_kernel<<<(num_node + GBM - 1) / GBM, 512, SMEM_BYTES>>>(
        pt, out, dup, num_node);
}

// round 9
// speedup vs baseline: 2.6712x; 1.0282x over previous
#include <cuda_runtime.h>
#include <cuda_fp16.h>
#include <cstdint>

// ---------------------------------------------------------------------------
// RGCN conv with history cache.
//   out[n] = history_buffer[n]                       if history_map[n] != -1
//   out[n] = (1/deg) * sum_r A_r[n] @ W_r            otherwise
// Aggregate per-relation sums (fp32 accum) into compacted rows, round to a
// single fp16 plane; GEMM = A@W in plain fp16 mma.sync (rel_err ~5e-5).
// Round 9: aggregate cp.async split into 2 pipelined groups + 128-thr blocks;
// detect_reset merged into wprep.
// ---------------------------------------------------------------------------

#define MAX_NODE 100000
#define PAD_ROWS (MAX_NODE + 256)
#define HID 128
#define NUM_REL 8
#define KDIM (NUM_REL * HID)   // 1024

__device__ __half g_Ah[(size_t)PAD_ROWS * KDIM];
__device__ __half g_Wh[(size_t)HID * KDIM];   // [n][k] (K-major)
__device__ int  g_active[MAX_NODE];
__device__ int  g_count;
__device__ int  g_is64;

// ======================= PTX helpers =======================================
__device__ __forceinline__ uint32_t smem_u32(const void* p) {
    uint32_t a;
    asm("{ .reg .u64 t; cvta.to.shared.u64 t, %1; cvt.u32.u64 %0, t; }"
        : "=r"(a) : "l"(p));
    return a;
}
#define CP16(dst, src) \
    asm volatile("cp.async.cg.shared.global [%0], [%1], 16;" \
        :: "r"(dst), "l"(src) : "memory")
#define CP_COMMIT() asm volatile("cp.async.commit_group;" ::: "memory")
#define CP_WAIT(n)  asm volatile("cp.async.wait_group %0;" :: "n"(n) : "memory")
#define CP_WAIT_ALL() asm volatile("cp.async.wait_all;" ::: "memory")

#define LDSM4(r, a)                                                           \
    asm volatile("ldmatrix.sync.aligned.m8n8.x4.shared.b16 {%0,%1,%2,%3}, [%4];" \
        : "=r"((r)[0]), "=r"((r)[1]), "=r"((r)[2]), "=r"((r)[3]) : "r"(a))

#define MMA16816F16(c, a, b0, b1)                                             \
    asm volatile("mma.sync.aligned.m16n8k16.row.col.f32.f16.f16.f32 "         \
        "{%0,%1,%2,%3}, {%4,%5,%6,%7}, {%8,%9}, {%0,%1,%2,%3};"               \
        : "+f"((c)[0]), "+f"((c)[1]), "+f"((c)[2]), "+f"((c)[3])              \
        : "r"((a)[0]), "r"((a)[1]), "r"((a)[2]), "r"((a)[3]),                 \
          "r"(b0), "r"(b1))

// ===========================================================================
// W prep (transpose [1024,128] fp32 -> [128][1024] fp16) + reset/detect.
__global__ void wprep_kernel(const float* __restrict__ W,
                             const void* __restrict__ ptrv) {
    if (blockIdx.x == 0 && threadIdx.x == 0) {
        g_count = 0;
        // ptr[0]==0; int64 -> word[1] is high half of 0; int32 -> deg>=1.
        g_is64 = (((const int*)ptrv)[1] == 0) ? 1 : 0;
    }
    int i = blockIdx.x * blockDim.x + threadIdx.x;
    if (i >= KDIM * HID) return;
    int k = i >> 7, n = i & 127;
    g_Wh[(size_t)n * KDIM + k] = __float2half(W[i]);
}

// ---------------------------------------------------------------------------
__global__ void compact_history_kernel(const void* __restrict__ hmv,
                                       const float* __restrict__ hb,
                                       float* __restrict__ out,
                                       int dup, int num_node) {
    int w    = (int)((blockIdx.x * blockDim.x + threadIdx.x) >> 5);
    int lane = threadIdx.x & 31;
    if (w >= num_node) return;
    long long m = g_is64 ? ((const long long*)hmv)[w]
                         : (long long)((const int*)hmv)[w];
    if (m != -1LL) {
        float4 v = *(const float4*)(hb + (size_t)w * HID + lane * 4);
        *(float4*)(out + (size_t)w * HID + lane * 4) = v;
        if (dup)
            *(float4*)(out + (size_t)(w + num_node) * HID + lane * 4) = v;
    } else if (lane == 0) {
        int slot = atomicAdd(&g_count, 1);
        g_active[slot] = w;
    }
}

// ---------------------------------------------------------------------------
// Aggregate: one warp per node; gathers staged through smem via cp.async in
// two pipelined groups of 8 (accumulate group 0 while group 1 in flight).
__device__ __forceinline__ void store_h(float4 a, size_t off) {
    __half h0 = __float2half(a.x), h1 = __float2half(a.y);
    __half h2 = __float2half(a.z), h3 = __float2half(a.w);
    uint2 uh;
    uh.x = ((uint32_t)__half_as_ushort(h1) << 16) | __half_as_ushort(h0);
    uh.y = ((uint32_t)__half_as_ushort(h3) << 16) | __half_as_ushort(h2);
    *(uint2*)((__half*)g_Ah + off) = uh;
}

#define ACC_CASE(r, a)                                                        \
    case r: a.x += v_.x; a.y += v_.y; a.z += v_.z; a.w += v_.w; break;

#define AGG_CHUNK 16
#define AGG_ROWB  (AGG_CHUNK * HID)     // floats per warp buffer
#define AGG_THREADS 128
#define AGG_WARPS   (AGG_THREADS / 32)
#define AGG_SMEM (AGG_WARPS * AGG_ROWB * 4)   // 32768 bytes

__global__ __launch_bounds__(AGG_THREADS)
void aggregate_kernel(const float* __restrict__ x,
                      const void* __restrict__ ptrv,
                      const void* __restrict__ idxv,
                      const void* __restrict__ etv) {
    extern __shared__ float sbuf[];     // 4 warps * 16 rows * 512B = 32 KB
    int w    = (int)((blockIdx.x * blockDim.x + threadIdx.x) >> 5);
    int lane = threadIdx.x & 31;
    if (w >= g_count) return;
    int is64 = g_is64;
    int node = g_active[w];

    long long p0, p1;
    if (is64) {
        p0 = ((const long long*)ptrv)[node];
        p1 = ((const long long*)ptrv)[node + 1];
    } else {
        p0 = ((const int*)ptrv)[node];
        p1 = ((const int*)ptrv)[node + 1];
    }

    float*   mybuf  = sbuf + (size_t)(threadIdx.x >> 5) * AGG_ROWB;
    uint32_t sm     = smem_u32(mybuf);

    float4 a0 = {0,0,0,0}, a1 = {0,0,0,0}, a2 = {0,0,0,0}, a3 = {0,0,0,0};
    float4 a4 = {0,0,0,0}, a5 = {0,0,0,0}, a6 = {0,0,0,0}, a7 = {0,0,0,0};

    for (long long c0 = p0; c0 < p1; c0 += AGG_CHUNK) {
        int n = (int)((p1 - c0) < AGG_CHUNK ? (p1 - c0) : AGG_CHUNK);
        long long s_l = 0; int t_l = 0;
        if (lane < n) {
            long long e = c0 + lane;
            s_l = is64 ? ((const long long*)idxv)[e]
                       : (long long)((const int*)idxv)[e];
            t_l = is64 ? (int)((const long long*)etv)[e]
                       : ((const int*)etv)[e];
        }
        if (n == AGG_CHUNK) {
            // group 0: edges 0..7
            #pragma unroll
            for (int e = 0; e < 8; e++) {
                long long src = __shfl_sync(0xffffffffu, s_l, e);
                CP16(sm + (uint32_t)(e * 512 + lane * 16),
                     x + (size_t)src * HID + lane * 4);
            }
            CP_COMMIT();
            // group 1: edges 8..15
            #pragma unroll
            for (int e = 8; e < 16; e++) {
                long long src = __shfl_sync(0xffffffffu, s_l, e);
                CP16(sm + (uint32_t)(e * 512 + lane * 16),
                     x + (size_t)src * HID + lane * 4);
            }
            CP_COMMIT();
            // consume group 0 while group 1 is in flight
            CP_WAIT(1);
            __syncwarp();
            #pragma unroll
            for (int e = 0; e < 8; e++) {
                int ty = __shfl_sync(0xffffffffu, t_l, e);
                float4 v_ = *(const float4*)(mybuf + e * HID + lane * 4);
                switch (ty) {
                    ACC_CASE(0, a0) ACC_CASE(1, a1) ACC_CASE(2, a2) ACC_CASE(3, a3)
                    ACC_CASE(4, a4) ACC_CASE(5, a5) ACC_CASE(6, a6) ACC_CASE(7, a7)
                    default: break;
                }
            }
            CP_WAIT(0);
            __syncwarp();
            #pragma unroll
            for (int e = 8; e < 16; e++) {
                int ty = __shfl_sync(0xffffffffu, t_l, e);
                float4 v_ = *(const float4*)(mybuf + e * HID + lane * 4);
                switch (ty) {
                    ACC_CASE(0, a0) ACC_CASE(1, a1) ACC_CASE(2, a2) ACC_CASE(3, a3)
                    ACC_CASE(4, a4) ACC_CASE(5, a5) ACC_CASE(6, a6) ACC_CASE(7, a7)
                    default: break;
                }
            }
        } else {
            for (int e = 0; e < n; e++) {
                long long src = __shfl_sync(0xffffffffu, s_l, e);
                CP16(sm + (uint32_t)(e * 512 + lane * 16),
                     x + (size_t)src * HID + lane * 4);
            }
            CP_WAIT_ALL();
            __syncwarp();
            for (int e = 0; e < n; e++) {
                int ty = __shfl_sync(0xffffffffu, t_l, e);
                float4 v_ = *(const float4*)(mybuf + e * HID + lane * 4);
                switch (ty) {
                    ACC_CASE(0, a0) ACC_CASE(1, a1) ACC_CASE(2, a2) ACC_CASE(3, a3)
                    ACC_CASE(4, a4) ACC_CASE(5, a5) ACC_CASE(6, a6) ACC_CASE(7, a7)
                    default: break;
                }
            }
        }
        __syncwarp();
    }

    size_t base = (size_t)w * KDIM + lane * 4;
    store_h(a0, base + 0 * HID);  store_h(a1, base + 1 * HID);
    store_h(a2, base + 2 * HID);  store_h(a3, base + 3 * HID);
    store_h(a4, base + 4 * HID);  store_h(a5, base + 5 * HID);
    store_h(a6, base + 6 * HID);  store_h(a7, base + 7 * HID);
}

// ---------------------------------------------------------------------------
// mma.sync GEMM: [count,1024](A fp16) @ [1024,128](W fp16), single term.
// CTA 256x128 (512 thr, 16 warps, warp 64x32), k-tile 64, double-buffered.
#define GBM 256
#define GBK 64
#define NT (KDIM / GBK)                // 16 k-tiles
#define TPA (GBM * GBK * 2)            // 32768 bytes A tile
#define TPB (HID * GBK * 2)            // 16384 bytes B tile
#define S_AH 0
#define S_BH TPA
#define STAGE_B (TPA + TPB)            // 49152 per stage
#define SMEM_BYTES (2 * STAGE_B)       // 98304

// swizzled byte offset within a [rows][64 f16] tile (row stride 128B, SW128)
__device__ __forceinline__ uint32_t swz(uint32_t row, uint32_t chunk) {
    return row * 128u + ((chunk ^ (row & 7u)) << 4);
}

__global__ __launch_bounds__(512, 1)
void gemm_mma_kernel(const void* __restrict__ ptrv,
                     float* __restrict__ out,
                     int dup, int num_node) {
    extern __shared__ __align__(1024) char smem[];
    int count = g_count;
    int m0 = blockIdx.x * GBM;
    if (m0 >= count) return;

    uint32_t sb = smem_u32(smem);
    int t = threadIdx.x, wid = t >> 5, lane = t & 31;
    int wm = wid >> 2;                 // 0..3  (m block of 64)
    int wn = wid & 3;                  // 0..3  (n block of 32)

    const __half* pAh = (const __half*)g_Ah;
    const __half* pWh = (const __half*)g_Wh;

    int ltile = lane >> 3, lrow = lane & 7;

    float acc[4][4][4];
    #pragma unroll
    for (int i = 0; i < 4; i++)
        #pragma unroll
        for (int j = 0; j < 4; j++)
            #pragma unroll
            for (int q = 0; q < 4; q++) acc[i][j][q] = 0.f;

    auto load_stage = [&](int kt) {
        uint32_t stg = sb + (kt & 1) * STAGE_B;
        size_t kofs = (size_t)kt * GBK;
        #pragma unroll
        for (int i = 0; i < 4; i++) {
            int id  = t + i * 512;          // 0..2047
            int row = id >> 3;              // 0..255
            int c   = id & 7;
            uint32_t sw = swz(row, c);
            size_t ga = (size_t)(m0 + row) * KDIM + kofs + c * 8;
            CP16(stg + S_AH + sw, pAh + ga);
        }
        #pragma unroll
        for (int i = 0; i < 2; i++) {
            int id  = t + i * 512;          // 0..1023
            int row = id >> 3;              // 0..127
            int c   = id & 7;
            uint32_t sw = swz(row, c);
            size_t gw = (size_t)row * KDIM + kofs + c * 8;
            CP16(stg + S_BH + sw, pWh + gw);
        }
        CP_COMMIT();
    };

    load_stage(0);

    for (int kt = 0; kt < NT; kt++) {
        if (kt + 1 < NT) { load_stage(kt + 1); CP_WAIT(1); }
        else            { CP_WAIT(0); }
        __syncthreads();

        uint32_t stg = sb + (kt & 1) * STAGE_B;
        #pragma unroll
        for (int ks = 0; ks < 4; ks++) {
            int cch = ks * 2 + (ltile >> 1);
            uint32_t bh[2][4];
            #pragma unroll
            for (int j = 0; j < 2; j++) {
                uint32_t r = wn * 32 + j * 16 + (ltile & 1) * 8 + lrow;
                uint32_t sw = swz(r, (uint32_t)cch);
                LDSM4(bh[j], stg + S_BH + sw);
            }
            #pragma unroll
            for (int mf = 0; mf < 4; mf++) {
                uint32_t ah[4];
                uint32_t r = wm * 64 + mf * 16 + (ltile & 1) * 8 + lrow;
                uint32_t sw = swz(r, (uint32_t)cch);
                LDSM4(ah, stg + S_AH + sw);
                #pragma unroll
                for (int nf = 0; nf < 4; nf++) {
                    int hj = nf >> 1, ho = nf & 1;
                    MMA16816F16(acc[mf][nf], ah, bh[hj][ho], bh[hj][ho + 2]);
                }
            }
        }
        __syncthreads();
    }

    // ---- epilogue: 1/deg scale + scatter (both output halves) ----
    int g  = lane >> 2;
    int tq = lane & 3;
    int is64 = g_is64;
    #pragma unroll
    for (int mf = 0; mf < 4; mf++) {
        int m_lo = m0 + wm * 64 + mf * 16 + g;       // rows g and g+8
        #pragma unroll
        for (int half = 0; half < 2; half++) {
            int m = m_lo + half * 8;
            if (m >= count) continue;
            int node = g_active[m];
            long long d;
            if (is64)
                d = ((const long long*)ptrv)[node + 1] - ((const long long*)ptrv)[node];
            else
                d = (long long)(((const int*)ptrv)[node + 1] - ((const int*)ptrv)[node]);
            float inv = 1.0f / (float)d;
            #pragma unroll
            for (int nf = 0; nf < 4; nf++) {
                float2 v;
                v.x = acc[mf][nf][half * 2 + 0] * inv;
                v.y = acc[mf][nf][half * 2 + 1] * inv;
                size_t co = (size_t)node * HID + wn * 32 + nf * 8 + tq * 2;
                *(float2*)(out + co) = v;
                if (dup)
                    *(float2*)(out + co + (size_t)num_node * HID) = v;
            }
        }
    }
}

// ---------------------------------------------------------------------------
extern "C" void kernel_launch(void* const* d_in, const int* in_sizes, int n_in,
                              void* d_out, int out_size) {
    const float* x  = (const float*)d_in[0];
    const float* W  = (const float*)d_in[1];   // [8,128,128] == [1024,128]
    const void*  pt = d_in[2];
    const void*  ix = d_in[3];
    const void*  et = d_in[4];
    const void*  hm = d_in[5];
    const float* hb = (const float*)d_in[6];
    float* out = (float*)d_out;

    int num_node = in_sizes[0] / HID;
    long long need2 = 2LL * (long long)num_node * HID;
    int dup = ((long long)out_size >= need2) ? 1 : 0;

    cudaFuncSetAttribute(gemm_mma_kernel,
                         cudaFuncAttributeMaxDynamicSharedMemorySize, SMEM_BYTES);
    cudaFuncSetAttribute(aggregate_kernel,
                         cudaFuncAttributeMaxDynamicSharedMemorySize, AGG_SMEM);

    wprep_kernel<<<(KDIM * HID + 255) / 256, 256>>>(W, pt);

    int warp_blocks = (num_node * 32 + 255) / 256;
    compact_history_kernel<<<warp_blocks, 256>>>(hm, hb, out, dup, num_node);

    int agg_blocks = (num_node * 32 + AGG_THREADS - 1) / AGG_THREADS;
    aggregate_kernel<<<agg_blocks, AGG_THREADS, AGG_SMEM>>>(x, pt, ix, et);

    gemm_mma_kernel<<<(num_node + GBM - 1) / GBM, 512, SMEM_BYTES>>>(
        pt, out, dup, num_node);
}